// round 11
// baseline (speedup 1.0000x reference)
#include <cuda_runtime.h>

// Profile-HMM forward NLL + KLD -- wavefront, scaled linear domain, f32x2.
// 512 one-warp blocks. Lane owns k = 2*lane+1, 2*lane+2. Slot1/slot2 cells
// are computed jointly with packed fma.rn.f32x2 / mul.rn.f32x2 (Blackwell).
// Deferred power-of-2 rescale every 4 diagonals via redux.sync (lossless);
// the warp max is taken on PRE-scale values with exponent compensation.

#define FULLMASK 0xffffffffu
#define LN2 0.69314718055994531f

typedef unsigned long long ull;

__device__ float g_vb[512];
__device__ unsigned int g_cnt = 0;

__device__ __forceinline__ ull pk2(float x, float y) {
    ull r; asm("mov.b64 %0, {%1, %2};" : "=l"(r) : "f"(x), "f"(y)); return r;
}
__device__ __forceinline__ void upk2(float& x, float& y, ull v) {
    asm("mov.b64 {%0, %1}, %2;" : "=f"(x), "=f"(y) : "l"(v));
}
__device__ __forceinline__ ull fma2(ull a, ull b, ull c) {
    ull r; asm("fma.rn.f32x2 %0, %1, %2, %3;" : "=l"(r) : "l"(a), "l"(b), "l"(c)); return r;
}
__device__ __forceinline__ ull mul2(ull a, ull b) {
    ull r; asm("mul.rn.f32x2 %0, %1, %2;" : "=l"(r) : "l"(a), "l"(b)); return r;
}
__device__ __forceinline__ unsigned warp_max_u32(unsigned v) {
    unsigned r;
    asm volatile("redux.sync.max.u32 %0, %1, 0xffffffff;" : "=r"(r) : "r"(v));
    return r;
}

__global__ void __launch_bounds__(32) phmm_kernel(
    const int*   __restrict__ binput,    // (B, 256)
    const float* __restrict__ trans,     // (B, 65, 7) log-probs (nats)
    const float* __restrict__ emis,      // (B, 64, 4) log-probs (nats)
    const float* __restrict__ mus,       // (B, 16)
    const float* __restrict__ logvars,   // (B, 16)
    float*       __restrict__ out)
{
    constexpr int L = 256;
    constexpr int K = 64;
    const int b    = blockIdx.x;
    const int lane = threadIdx.x;

    // s_co_p: 64 front-pad + 256 symbols + back-pad; value = symbol*256
    // (byte offset of the symbol's row in ep[], rows are 32 float2 = 256 B)
    __shared__ int    s_co_p[416];
    __shared__ float2 ep[128];           // [4 symbols][32 lanes] {e1, e2}

    const int* bi = binput + b * L;
#pragma unroll
    for (int i = 0; i < 13; ++i) {
        const int idx = lane + 32 * i;   // covers [0, 416)
        int v = 0;
        if (idx >= 64 && idx < 320) v = bi[idx - 64] << 8;
        s_co_p[idx] = v;
    }

    const float* a  = trans + b * 65 * 7;
    const float* em = emis  + b * 64 * 4;

    const int k1 = 2 * lane + 1;                // slot1 owns k1, slot2 owns k1+1
    const float* r0 = a + (k1 - 1) * 7;         // transition row k1-1
    const float* r1 = r0 + 7;                   // row k1 (= row k2-1)
    const float* r2 = r1 + 7;                   // row k2

    // indices: M2M=0, M2I=1, M2D=2, I2M=3, I2I=4, D2M=5, D2D=6
    // LOG_Q (q=0.25) folded into aMI/aII. Coefficients packed {slot1, slot2}.
    const ull AMM = pk2(expf(r0[0]), expf(r1[0]));
    const ull AIM = pk2(expf(r0[3]), expf(r1[3]));
    const ull ADM = pk2(expf(r0[5]), expf(r1[5]));
    const ull AMD = pk2(expf(r0[2]), expf(r1[2]));
    const ull ADD = pk2(expf(r0[6]), expf(r1[6]));
    const ull AMI = pk2(0.25f * expf(r1[1]), 0.25f * expf(r2[1]));
    const ull AII = pk2(0.25f * expf(r1[4]), 0.25f * expf(r2[4]));
    const float aMI0 = 0.25f * expf(a[1]), aII0 = 0.25f * expf(a[4]);   // row 0

#pragma unroll
    for (int c = 0; c < 4; ++c)
        ep[c * 32 + lane] = make_float2(expf(em[(k1 - 1) * 4 + c]),
                                        expf(em[k1 * 4 + c]));
    __syncwarp();

    // loop-carried state (all scaled by 2^Sacc relative to absolute probs)
    ull CM = pk2(0.f, 0.f), CI = CM, CD = CM;   // cur pairs (diag t-1)
    float pm = 0.f, pi = 0.f, pd = 0.f;         // prev slot1 (diag t-2)
    const float M00 = 1.152921504606847e18f;    // M(0,0) = 1 * 2^60
    float inj   = exp2f(-84.26950408889634f);   // e^-100 * 2^60  (NEG boundary)
    float k0I   = inj;                          // I(0,0) = NEG
    float mprev = M00;
    int   Sacc  = 60;
    float sc_ap = 1.0f;                         // deferred rescale
    int   se_ap = 0;

    // primed neighbors for t=1 (diag 0): lane-1 state zero; lane0 = k0 column
    float nM = (lane == 0) ? M00 : 0.f;
    float nI = (lane == 0) ? inj : 0.f;
    float nD = (lane == 0) ? inj : 0.f;
    float qM = 0.f, qI = 0.f, qD = 0.f;  // diag -1 neighbors: dead

    // emission pipeline priming
    const char* epb = (const char*)ep + lane * 8;
    int        off_p = s_co_p[65 - k1];
    const int* sp    = &s_co_p[66 - k1];
    float2     P     = *(const float2*)(epb + s_co_p[64 - k1]);
    float      e2c   = 0.0f;             // e2(1) is don't-care (cell dead)

#pragma unroll 4
    for (int t = 1; t <= L + K; ++t) {
        const int l1 = t - k1;
        float cM1, cM2u, cI1, cI2u, cD1, cD2u;
        upk2(cM1, cM2u, CM); upk2(cI1, cI2u, CI); upk2(cD1, cD2u, CD);

        // packed operands: {slot1, slot2}
        const ull QM = pk2(qM, pm), QI = pk2(qI, pi), QD = pk2(qD, pd);
        const ull NM = pk2(nM, cM1), ND = pk2(nD, cD1);
        const ull E  = pk2(P.x, e2c);

        const ull MG = mul2(E, fma2(ADM, QD, fma2(AIM, QI, mul2(AMM, QM))));
        const ull IG = fma2(AII, CI, mul2(AMI, CM));
        const ull DN = fma2(ADD, ND, mul2(AMD, NM));

        float M1g, M2g, I1g, I2g, D1n, D2n;
        upk2(M1g, M2g, MG); upk2(I1g, I2g, IG); upk2(D1n, D2n, DN);

        const float M1n = (l1 == 0) ? inj : M1g;
        const float I1n = (l1 == 0) ? inj : I1g;
        const float M2n = (l1 == 1) ? inj : M2g;
        const float I2n = (l1 == 1) ? inj : I2g;

        // rotation (prev slot1 <- cur slot1; cur <- new; q <- old n)
        pm = cM1; pi = cI1; pd = cD1;
        CM = pk2(M1n, M2n); CI = pk2(I1n, I2n); CD = DN;
        qM = nM; qI = nI; qD = nD;

        // k=0 column advance to diag t
        k0I = fmaf(aII0, k0I, aMI0 * mprev);
        mprev = inj;

        // shuffle neighbor values for iter t+1 (consumed a full iter later)
        nM = __shfl_up_sync(FULLMASK, M2n, 1);
        nI = __shfl_up_sync(FULLMASK, I2n, 1);
        nD = __shfl_up_sync(FULLMASK, D2n, 1);
        if (lane == 0) { nM = mprev; nI = k0I; nD = inj; }

        // emission prefetch advance
        e2c = P.y;
        P = *(const float2*)(epb + off_p);
        off_p = *sp++;

        // ---- deferred power-of-2 rescale every 4 diagonals ----
        if ((t & 3) == 0) {
            // warp max on PRE-scale values; exponent compensated below
            float m = fmaxf(fmaxf(M1n, M2n), fmaxf(I1n, I2n));
            m = fmaxf(m, fmaxf(D1n, D2n));
            m = fmaxf(m, k0I);
            // apply the scale computed at the PREVIOUS window
            const ull SC = pk2(sc_ap, sc_ap);
            CM = mul2(CM, SC); CI = mul2(CI, SC); CD = mul2(CD, SC);
            pm *= sc_ap; pi *= sc_ap; pd *= sc_ap;
            qM *= sc_ap; qI *= sc_ap; qD *= sc_ap;
            nM *= sc_ap; nI *= sc_ap; nD *= sc_ap;
            k0I *= sc_ap; mprev *= sc_ap; inj *= sc_ap;
            Sacc += se_ap;
            const unsigned mu32 = warp_max_u32(__float_as_uint(m));
            const int E2 = (int)(mu32 >> 23) & 0xFF;           // pre-scale exp
            int se = 187 - E2 - se_ap;                         // post-scale comp
            se = min(max(se, 0), 63);                          // overflow-proof
            se_ap = se;
            sc_ap = __int_as_float((se + 127) << 23);          // 2^se (exact)
        }
    }

    // lane 31 slot2 holds (M, I, D) at (L, K); broadcast to all lanes
    float xM1, xM2, xI1, xI2, xD1, xD2;
    upk2(xM1, xM2, CM); upk2(xI1, xI2, CI); upk2(xD1, xD2, CD);
    const float MF = __shfl_sync(FULLMASK, xM2, 31);
    const float IF = __shfl_sync(FULLMASK, xI2, 31);
    const float DF = __shfl_sync(FULLMASK, xD2, 31);
    const float fM = expf(a[K * 7 + 0]);
    const float fI = expf(a[K * 7 + 3]);
    const float fD = expf(a[K * 7 + 5]);
    const float sum = fmaf(fD, DF, fmaf(fI, IF, fM * MF));
    const float nll = -(log2f(sum) - (float)Sacc) * LN2;

    // KLD term: -0.5 * sum_e (1 + lv - mu^2 - exp(lv))
    float term = 0.0f;
    if (lane < 16) {
        const float mu = mus[b * 16 + lane];
        const float lv = logvars[b * 16 + lane];
        term = 1.0f + lv - mu * mu - expf(lv);
    }
#pragma unroll
    for (int o = 16; o > 0; o >>= 1) term += __shfl_xor_sync(FULLMASK, term, o);

    if (lane == 0) g_vb[b] = nll - 0.5f * term;

    // ---- last-block-done final reduction (deterministic fixed-order sum) ----
    __threadfence();
    unsigned int old = 0;
    if (lane == 0) old = atomicAdd(&g_cnt, 1u);
    old = __shfl_sync(FULLMASK, old, 0);
    if (old == gridDim.x - 1) {
        __threadfence();
        float s = 0.0f;
#pragma unroll
        for (int i = 0; i < 16; ++i) s += g_vb[lane + 32 * i];
#pragma unroll
        for (int o = 16; o > 0; o >>= 1) s += __shfl_xor_sync(FULLMASK, s, o);
        if (lane == 0) { out[0] = s * (1.0f / 512.0f); g_cnt = 0; }
    }
}

extern "C" void kernel_launch(void* const* d_in, const int* in_sizes, int n_in,
                              void* d_out, int out_size) {
    const int*   batch_input = (const int*)  d_in[0];
    const float* trans       = (const float*)d_in[1];
    const float* emisp       = (const float*)d_in[2];
    const float* mus         = (const float*)d_in[3];
    const float* logvars     = (const float*)d_in[4];
    (void)in_sizes; (void)n_in; (void)out_size;

    phmm_kernel<<<512, 32>>>(batch_input, trans, emisp, mus, logvars, (float*)d_out);
}

// round 12
// speedup vs baseline: 1.1182x; 1.1182x over previous
#include <cuda_runtime.h>

// Profile-HMM forward NLL + KLD -- wavefront, scaled linear domain.
// 512 one-warp blocks. Lane owns k = 2*lane+1, 2*lane+2. Probabilities linear;
// deferred power-of-2 rescale every 4 diagonals via redux.sync (lossless).
// Loop is phase-split: boundary forcing (l==0/1) only exists for t<=64, so
// the main phase (t=65..320) runs a select-free body at unroll 8.

#define FULLMASK 0xffffffffu
#define LN2 0.69314718055994531f

__device__ float g_vb[512];
__device__ unsigned int g_cnt = 0;

__device__ __forceinline__ unsigned warp_max_u32(unsigned v) {
    unsigned r;
    asm volatile("redux.sync.max.u32 %0, %1, 0xffffffff;" : "=r"(r) : "r"(v));
    return r;
}

__global__ void __launch_bounds__(32) phmm_kernel(
    const int*   __restrict__ binput,    // (B, 256)
    const float* __restrict__ trans,     // (B, 65, 7) log-probs (nats)
    const float* __restrict__ emis,      // (B, 64, 4) log-probs (nats)
    const float* __restrict__ mus,       // (B, 16)
    const float* __restrict__ logvars,   // (B, 16)
    float*       __restrict__ out)
{
    constexpr int L = 256;
    constexpr int K = 64;
    const int b    = blockIdx.x;
    const int lane = threadIdx.x;

    // s_co_p: 64 front-pad + 256 symbols + back-pad, value = symbol*32
    __shared__ int    s_co_p[416];
    __shared__ float2 ep[128];           // [4 symbols][32 lanes] {e1, e2}

    const int* bi = binput + b * L;
#pragma unroll
    for (int i = 0; i < 13; ++i) {
        const int idx = lane + 32 * i;   // covers [0, 416)
        int v = 0;
        if (idx >= 64 && idx < 320) v = bi[idx - 64] << 5;
        s_co_p[idx] = v;
    }

    const float* a  = trans + b * 65 * 7;
    const float* em = emis  + b * 64 * 4;

    const int k1 = 2 * lane + 1;                // slot1 owns k1, slot2 owns k1+1
    const float* r0 = a + (k1 - 1) * 7;         // transition row k1-1
    const float* r1 = r0 + 7;                   // row k1 (= row k2-1)
    const float* r2 = r1 + 7;                   // row k2

    // indices: M2M=0, M2I=1, M2D=2, I2M=3, I2I=4, D2M=5, D2D=6
    // LOG_Q (q=0.25) folded into aMI/aII.
    const float aMM1 = expf(r0[0]), aMD1 = expf(r0[2]);
    const float aIM1 = expf(r0[3]), aDM1 = expf(r0[5]), aDD1 = expf(r0[6]);
    const float aMI1 = 0.25f * expf(r1[1]), aII1 = 0.25f * expf(r1[4]);
    const float aMM2 = expf(r1[0]), aMD2 = expf(r1[2]);
    const float aIM2 = expf(r1[3]), aDM2 = expf(r1[5]), aDD2 = expf(r1[6]);
    const float aMI2 = 0.25f * expf(r2[1]), aII2 = 0.25f * expf(r2[4]);
    const float aMI0 = 0.25f * expf(a[1]),  aII0 = 0.25f * expf(a[4]);   // row 0

#pragma unroll
    for (int c = 0; c < 4; ++c)
        ep[c * 32 + lane] = make_float2(expf(em[(k1 - 1) * 4 + c]),
                                        expf(em[k1 * 4 + c]));
    __syncwarp();

    // loop-carried state (all scaled by 2^Sacc relative to absolute probs)
    float cM1 = 0.f, cI1 = 0.f, cD1 = 0.f, pM1 = 0.f, pI1 = 0.f, pD1 = 0.f;
    float cM2 = 0.f, cI2 = 0.f, cD2 = 0.f, pM2 = 0.f, pI2 = 0.f, pD2 = 0.f;
    const float M00 = 1.152921504606847e18f;    // M(0,0) = 1 * 2^60
    float inj   = exp2f(-84.26950408889634f);   // e^-100 * 2^60  (NEG boundary)
    float k0I   = inj;                          // I(0,0) = NEG
    float mprev = M00;
    int   Sacc  = 60;
    float sc_ap = 1.0f;                         // deferred rescale
    int   se_ap = 0;

    // primed neighbors for t=1 (diag 0): lane-1 state zero; lane0 = k0 column
    float nM = (lane == 0) ? M00 : 0.f;
    float nI = (lane == 0) ? inj : 0.f;
    float nD = (lane == 0) ? inj : 0.f;
    float qM = 0.f, qI = 0.f, qD = 0.f;  // diag -1 neighbors: dead

    // emission pipeline priming
    int    off_p = s_co_p[65 - k1];
    float2 P     = ep[s_co_p[64 - k1] + lane];
    float  e2c   = 0.0f;                // e2(1) is don't-care (cell dead)

    // ================= phase 1: t = 1..64 (boundary forcing live) ==========
#pragma unroll 4
    for (int t = 1; t <= 64; ++t) {
        const float e1 = P.x;
        const float e2 = e2c;
        const int l1 = t - k1;

        float M1g = e1 * fmaf(aDM1, qD, fmaf(aIM1, qI, aMM1 * qM));
        float I1g = fmaf(aII1, cI1, aMI1 * cM1);
        float D1n = fmaf(aDD1, nD, aMD1 * nM);
        float M1n = (l1 == 0) ? inj : M1g;
        float I1n = (l1 == 0) ? inj : I1g;

        float M2g = e2 * fmaf(aDM2, pD1, fmaf(aIM2, pI1, aMM2 * pM1));
        float I2g = fmaf(aII2, cI2, aMI2 * cM2);
        float D2n = fmaf(aDD2, cD1, aMD2 * cM1);
        float M2n = (l1 == 1) ? inj : M2g;
        float I2n = (l1 == 1) ? inj : I2g;

        pM2 = cM2; pI2 = cI2; pD2 = cD2; cM2 = M2n; cI2 = I2n; cD2 = D2n;
        pM1 = cM1; pI1 = cI1; pD1 = cD1; cM1 = M1n; cI1 = I1n; cD1 = D1n;
        qM = nM; qI = nI; qD = nD;

        k0I = fmaf(aII0, k0I, aMI0 * mprev);
        mprev = inj;

        nM = __shfl_up_sync(FULLMASK, cM2, 1);
        nI = __shfl_up_sync(FULLMASK, cI2, 1);
        nD = __shfl_up_sync(FULLMASK, cD2, 1);
        if (lane == 0) { nM = mprev; nI = k0I; nD = inj; }

        e2c = P.y;
        P = ep[off_p + lane];
        off_p = s_co_p[t - k1 + 65];

        if ((t & 3) == 0) {
            cM1 *= sc_ap; cI1 *= sc_ap; cD1 *= sc_ap;
            pM1 *= sc_ap; pI1 *= sc_ap; pD1 *= sc_ap;
            cM2 *= sc_ap; cI2 *= sc_ap; cD2 *= sc_ap;
            pM2 *= sc_ap; pI2 *= sc_ap; pD2 *= sc_ap;
            nM  *= sc_ap; nI  *= sc_ap; nD  *= sc_ap;
            qM  *= sc_ap; qI  *= sc_ap; qD  *= sc_ap;
            k0I *= sc_ap; mprev *= sc_ap; inj *= sc_ap;
            Sacc += se_ap;
            float m = fmaxf(fmaxf(cM1, cM2), fmaxf(cI1, cI2));
            m = fmaxf(m, fmaxf(cD1, cD2));
            m = fmaxf(m, k0I);
            const unsigned mu32 = warp_max_u32(__float_as_uint(m));
            const int E = (int)(mu32 >> 23) & 0xFF;
            int se = 187 - E;
            se = min(max(se, 0), 63);
            se_ap = se;
            sc_ap = __int_as_float((se + 127) << 23);
        }
    }

    // ================= phase 2: t = 65..320 (select-free body) =============
#pragma unroll 8
    for (int t = 65; t <= L + K; ++t) {
        const float e1 = P.x;
        const float e2 = e2c;

        float M1n = e1 * fmaf(aDM1, qD, fmaf(aIM1, qI, aMM1 * qM));
        float I1n = fmaf(aII1, cI1, aMI1 * cM1);
        float D1n = fmaf(aDD1, nD, aMD1 * nM);

        float M2n = e2 * fmaf(aDM2, pD1, fmaf(aIM2, pI1, aMM2 * pM1));
        float I2n = fmaf(aII2, cI2, aMI2 * cM2);
        float D2n = fmaf(aDD2, cD1, aMD2 * cM1);

        pM2 = cM2; pI2 = cI2; pD2 = cD2; cM2 = M2n; cI2 = I2n; cD2 = D2n;
        pM1 = cM1; pI1 = cI1; pD1 = cD1; cM1 = M1n; cI1 = I1n; cD1 = D1n;
        qM = nM; qI = nI; qD = nD;

        k0I = fmaf(aII0, k0I, aMI0 * mprev);
        mprev = inj;

        nM = __shfl_up_sync(FULLMASK, cM2, 1);
        nI = __shfl_up_sync(FULLMASK, cI2, 1);
        nD = __shfl_up_sync(FULLMASK, cD2, 1);
        if (lane == 0) { nM = mprev; nI = k0I; nD = inj; }

        e2c = P.y;
        P = ep[off_p + lane];
        off_p = s_co_p[t - k1 + 65];

        if ((t & 3) == 0) {
            cM1 *= sc_ap; cI1 *= sc_ap; cD1 *= sc_ap;
            pM1 *= sc_ap; pI1 *= sc_ap; pD1 *= sc_ap;
            cM2 *= sc_ap; cI2 *= sc_ap; cD2 *= sc_ap;
            pM2 *= sc_ap; pI2 *= sc_ap; pD2 *= sc_ap;
            nM  *= sc_ap; nI  *= sc_ap; nD  *= sc_ap;
            qM  *= sc_ap; qI  *= sc_ap; qD  *= sc_ap;
            k0I *= sc_ap; mprev *= sc_ap; inj *= sc_ap;
            Sacc += se_ap;
            float m = fmaxf(fmaxf(cM1, cM2), fmaxf(cI1, cI2));
            m = fmaxf(m, fmaxf(cD1, cD2));
            m = fmaxf(m, k0I);
            const unsigned mu32 = warp_max_u32(__float_as_uint(m));
            const int E = (int)(mu32 >> 23) & 0xFF;
            int se = 187 - E;
            se = min(max(se, 0), 63);
            se_ap = se;
            sc_ap = __int_as_float((se + 127) << 23);
        }
    }

    // lane 31 slot2 holds (M, I, D) at (L, K); broadcast to all lanes
    const float MF = __shfl_sync(FULLMASK, cM2, 31);
    const float IF = __shfl_sync(FULLMASK, cI2, 31);
    const float DF = __shfl_sync(FULLMASK, cD2, 31);
    const float fM = expf(a[K * 7 + 0]);
    const float fI = expf(a[K * 7 + 3]);
    const float fD = expf(a[K * 7 + 5]);
    const float sum = fmaf(fD, DF, fmaf(fI, IF, fM * MF));
    const float nll = -(log2f(sum) - (float)Sacc) * LN2;

    // KLD term: -0.5 * sum_e (1 + lv - mu^2 - exp(lv))
    float term = 0.0f;
    if (lane < 16) {
        const float mu = mus[b * 16 + lane];
        const float lv = logvars[b * 16 + lane];
        term = 1.0f + lv - mu * mu - expf(lv);
    }
#pragma unroll
    for (int o = 16; o > 0; o >>= 1) term += __shfl_xor_sync(FULLMASK, term, o);

    if (lane == 0) g_vb[b] = nll - 0.5f * term;

    // ---- last-block-done final reduction (deterministic fixed-order sum) ----
    __threadfence();
    unsigned int old = 0;
    if (lane == 0) old = atomicAdd(&g_cnt, 1u);
    old = __shfl_sync(FULLMASK, old, 0);
    if (old == gridDim.x - 1) {
        __threadfence();
        float s = 0.0f;
#pragma unroll
        for (int i = 0; i < 16; ++i) s += g_vb[lane + 32 * i];
#pragma unroll
        for (int o = 16; o > 0; o >>= 1) s += __shfl_xor_sync(FULLMASK, s, o);
        if (lane == 0) { out[0] = s * (1.0f / 512.0f); g_cnt = 0; }
    }
}

extern "C" void kernel_launch(void* const* d_in, const int* in_sizes, int n_in,
                              void* d_out, int out_size) {
    const int*   batch_input = (const int*)  d_in[0];
    const float* trans       = (const float*)d_in[1];
    const float* emisp       = (const float*)d_in[2];
    const float* mus         = (const float*)d_in[3];
    const float* logvars     = (const float*)d_in[4];
    (void)in_sizes; (void)n_in; (void)out_size;

    phmm_kernel<<<512, 32>>>(batch_input, trans, emisp, mus, logvars, (float*)d_out);
}